// round 6
// baseline (speedup 1.0000x reference)
#include <cuda_runtime.h>
#include <cstdint>

// Depthwise1d: out[n,c,o] = sum_i x[n,c,i] * W[c,o,i] + b[c,o]
// N=4096, C=256, K=64, O=128, fp32.
//
// R5: FFMA2 with f32x2 = row-pair; register tile r=8 rows x c=16 cols
// (8 rows = 4 planes x row-pair, planes +64 apart -> conflict-free LDS.64).
// One 256-thread CTA per SM, block tile 256 rows x 128 cols x 1 channel.

#define N_TOT   4096
#define C_TOT   256
#define K_IN    64
#define O_OUT   128
#define TILE_M  256
#define THREADS 256
#define XTS     258      // XT row stride in floats

// smem layout (bytes)
#define SM_BIAS  0                          // 512 B
#define SM_XT    512                        // 64 * 258 * 4 = 66048
#define SM_W     (SM_XT + 64 * XTS * 4)     // 66560 (16B aligned)
#define SM_TOTAL (SM_W + 128 * 64 * 4)      // 99328

__device__ __forceinline__ void ffma2(unsigned long long& d,
                                      unsigned long long a,
                                      unsigned long long b) {
    asm("fma.rn.f32x2 %0, %1, %2, %0;" : "+l"(d) : "l"(a), "l"(b));
}
__device__ __forceinline__ unsigned long long dup2(float w) {
    unsigned long long r;
    asm("mov.b64 %0, {%1, %1};" : "=l"(r) : "f"(w));
    return r;
}
__device__ __forceinline__ float2 unpack2(unsigned long long v) {
    float2 f;
    asm("mov.b64 {%0, %1}, %2;" : "=f"(f.x), "=f"(f.y) : "l"(v));
    return f;
}

__global__ __launch_bounds__(THREADS, 1)
void dw1d_kernel(const float* __restrict__ x,
                 const float* __restrict__ W,
                 const float* __restrict__ b,
                 float* __restrict__ out) {
    extern __shared__ float smem[];
    float* bias_sh = smem;                 // 128 floats
    float* XT      = smem + SM_XT / 4;     // [k][row], stride XTS
    float* Wsh     = smem + SM_W / 4;      // [o][k],   stride 64

    const int t   = threadIdx.x;
    const int wid = t >> 5;
    const int lid = t & 31;
    const int n0  = blockIdx.x * TILE_M;
    const int c   = blockIdx.y;

    if (t < O_OUT) bias_sh[t] = b[c * O_OUT + t];

    // ---- Stage x: transpose [row][k] -> XT[k][row] (row-pairs packed) ----
    {
        const int ku = t & 15;             // float4 chunk along k
        const int a0 = t >> 4;             // row-pair index base
#pragma unroll
        for (int j = 0; j < 8; ++j) {
            int a = a0 + 16 * j;           // row pair 0..127
            const float* p0 = x + ((size_t)(n0 + 2 * a) * C_TOT + c) * K_IN + 4 * ku;
            const float* p1 = p0 + (size_t)C_TOT * K_IN;
            float4 va = *(const float4*)p0;
            float4 vb = *(const float4*)p1;
            *(float2*)&XT[(4 * ku + 0) * XTS + 2 * a] = make_float2(va.x, vb.x);
            *(float2*)&XT[(4 * ku + 1) * XTS + 2 * a] = make_float2(va.y, vb.y);
            *(float2*)&XT[(4 * ku + 2) * XTS + 2 * a] = make_float2(va.z, vb.z);
            *(float2*)&XT[(4 * ku + 3) * XTS + 2 * a] = make_float2(va.w, vb.w);
        }
    }
    // ---- Stage W: [o][k] stride 64, float4 coalesced ----
    {
        const float* wbase = W + (size_t)c * O_OUT * K_IN;
#pragma unroll
        for (int j = 0; j < 8; ++j) {
            int idx = t + THREADS * j;     // 0..2047
            int o  = idx >> 4;
            int k4 = idx & 15;
            float4 v = *(const float4*)(wbase + (size_t)o * K_IN + 4 * k4);
            *(float4*)&Wsh[o * K_IN + 4 * k4] = v;
        }
    }
    __syncthreads();

    // ---- Compute: thread = 4 planes x row-pair (rows p*64 + 2*lid + {0,1})
    //               x 16 cols (colbase..colbase+15) ----
    unsigned long long acc[4][16];
#pragma unroll
    for (int p = 0; p < 4; ++p)
#pragma unroll
        for (int cc = 0; cc < 16; ++cc)
            acc[p][cc] = 0ULL;

    const int colbase = wid * 16;

#pragma unroll 2
    for (int k4 = 0; k4 < K_IN / 4; ++k4) {
        unsigned long long xv[4][4];       // [kk][plane]
#pragma unroll
        for (int kk = 0; kk < 4; ++kk) {
            const float* rowp = &XT[(4 * k4 + kk) * XTS + 2 * lid];
#pragma unroll
            for (int p = 0; p < 4; ++p)
                xv[kk][p] = *(const unsigned long long*)(rowp + 64 * p);
        }
#pragma unroll
        for (int cc = 0; cc < 16; ++cc) {
            float4 wq = *(const float4*)&Wsh[(colbase + cc) * K_IN + 4 * k4];
            unsigned long long w0 = dup2(wq.x);
            unsigned long long w1 = dup2(wq.y);
            unsigned long long w2 = dup2(wq.z);
            unsigned long long w3 = dup2(wq.w);
#pragma unroll
            for (int p = 0; p < 4; ++p) {
                ffma2(acc[p][cc], xv[0][p], w0);
                ffma2(acc[p][cc], xv[1][p], w1);
                ffma2(acc[p][cc], xv[2][p], w2);
                ffma2(acc[p][cc], xv[3][p], w3);
            }
        }
    }

    // ---- Epilogue ----
    float bb[16];
#pragma unroll
    for (int cc = 0; cc < 16; ++cc)
        bb[cc] = bias_sh[colbase + cc];

#pragma unroll
    for (int p = 0; p < 4; ++p) {
#pragma unroll
        for (int sel = 0; sel < 2; ++sel) {
            int n = n0 + p * 64 + 2 * lid + sel;
            float* orow = out + ((size_t)n * C_TOT + c) * O_OUT + colbase;
#pragma unroll
            for (int g = 0; g < 4; ++g) {
                float2 f0 = unpack2(acc[p][4 * g + 0]);
                float2 f1 = unpack2(acc[p][4 * g + 1]);
                float2 f2 = unpack2(acc[p][4 * g + 2]);
                float2 f3 = unpack2(acc[p][4 * g + 3]);
                float4 v;
                v.x = (sel ? f0.y : f0.x) + bb[4 * g + 0];
                v.y = (sel ? f1.y : f1.x) + bb[4 * g + 1];
                v.z = (sel ? f2.y : f2.x) + bb[4 * g + 2];
                v.w = (sel ? f3.y : f3.x) + bb[4 * g + 3];
                *(float4*)&orow[4 * g] = v;
            }
        }
    }
}

extern "C" void kernel_launch(void* const* d_in, const int* in_sizes, int n_in,
                              void* d_out, int out_size) {
    const float* x = (const float*)d_in[0];
    const float* W = (const float*)d_in[1];
    const float* b = (const float*)d_in[2];
    float* out = (float*)d_out;

    cudaFuncSetAttribute(dw1d_kernel,
                         cudaFuncAttributeMaxDynamicSharedMemorySize, SM_TOTAL);

    dim3 grid(N_TOT / TILE_M, C_TOT);
    dw1d_kernel<<<grid, THREADS, SM_TOTAL>>>(x, W, b, out);
}

// round 7
// speedup vs baseline: 1.8243x; 1.8243x over previous
#include <cuda_runtime.h>
#include <cstdint>

// Depthwise1d: out[n,c,o] = sum_i x[n,c,i] * W[c,o,i] + b[c,o]
// N=4096, C=256, K=64, O=128, fp32.
//
// R6: col-pair packed FFMA2 (acc f32x2 = adjacent output cols), r=8 x c=8,
// 16 warps/SM. W pre-transposed to k-major by a tiny helper kernel into
// __device__ scratch, so the main kernel has zero transposes:
//   x: natural Xsh[row][k], LDS.32 broadcast reads
//   W: Wsh[k][o], LDS.128 gives 2 col-pairs
//   epilogue: 2 coalesced STG.128 per row

#define N_TOT   4096
#define C_TOT   256
#define K_IN    64
#define O_OUT   128
#define TILE_M  128
#define THREADS 256
#define XSTR    68       // Xsh row stride (floats)
#define WSTR    132      // Wsh k-row stride (floats)

// 8 MB scratch: W2g[c][k][o]
__device__ float W2g[C_TOT * K_IN * O_OUT];

__device__ __forceinline__ void ffma2(unsigned long long& d,
                                      unsigned long long a,
                                      unsigned long long b) {
    asm("fma.rn.f32x2 %0, %1, %2, %0;" : "+l"(d) : "l"(a), "l"(b));
}
__device__ __forceinline__ unsigned long long dup2(float w) {
    unsigned long long r;
    asm("mov.b64 %0, {%1, %1};" : "=l"(r) : "f"(w));
    return r;
}
__device__ __forceinline__ float2 unpack2(unsigned long long v) {
    float2 f;
    asm("mov.b64 {%0, %1}, %2;" : "=f"(f.x), "=f"(f.y) : "l"(v));
    return f;
}

// ---- Kernel A: W[c][o][k] -> W2g[c][k][o] (tiny, ~5us) ----
__global__ __launch_bounds__(256)
void w_transpose(const float* __restrict__ W) {
    __shared__ float Wt[O_OUT * 68];       // [o][k] stride 68
    const int t = threadIdx.x;
    const int c = blockIdx.x;
#pragma unroll
    for (int j = 0; j < 8; ++j) {
        int idx = t + 256 * j;             // 0..2047
        int o = idx >> 4, q = idx & 15;
        float4 v = *(const float4*)(W + ((size_t)c * O_OUT + o) * K_IN + 4 * q);
        *(float4*)&Wt[o * 68 + 4 * q] = v;
    }
    __syncthreads();
    float* dst = W2g + (size_t)c * K_IN * O_OUT;
#pragma unroll
    for (int j = 0; j < 32; ++j) {
        int idx = t + 256 * j;             // 0..8191
        int k = idx >> 7, o = idx & 127;
        dst[k * O_OUT + o] = Wt[o * 68 + k];
    }
}

// ---- Kernel B: main GEMM ----
__global__ __launch_bounds__(THREADS, 2)
void dw1d_kernel(const float* __restrict__ x,
                 const float* __restrict__ b,
                 float* __restrict__ out) {
    extern __shared__ float smem[];
    float* bias_sh = smem;                       // 128 floats
    float* Xsh = smem + 128;                     // [row][k] stride 68
    float* Wsh = smem + 128 + TILE_M * XSTR;     // [k][o]  stride 132

    const int t  = threadIdx.x;
    const int cg = t & 15;
    const int rg = t >> 4;
    const int n0 = blockIdx.x * TILE_M;
    const int c  = blockIdx.y;

    if (t < O_OUT) bias_sh[t] = b[c * O_OUT + t];

    // stage x: coalesced LDG.128 -> Xsh[row][k]
    {
        const float* xb = x + (size_t)c * K_IN;
#pragma unroll
        for (int j = 0; j < 8; ++j) {
            int idx = t + THREADS * j;     // 0..2047
            int row = idx >> 4, ku = idx & 15;
            float4 v = *(const float4*)(xb + (size_t)(n0 + row) * C_TOT * K_IN + 4 * ku);
            *(float4*)&Xsh[row * XSTR + 4 * ku] = v;
        }
    }
    // stage W (already k-major): coalesced LDG.128 -> Wsh[k][o]
    {
        const float* wb = W2g + (size_t)c * K_IN * O_OUT;
#pragma unroll
        for (int j = 0; j < 8; ++j) {
            int idx = t + THREADS * j;     // 0..2047
            int k = idx >> 5, o4 = idx & 31;
            float4 v = *(const float4*)(wb + k * O_OUT + 4 * o4);
            *(float4*)&Wsh[k * WSTR + 4 * o4] = v;
        }
    }
    __syncthreads();

    // compute: rows r_i = rg + 16*i (i<8); cols 4cg..4cg+3 and 64+4cg..+3
    unsigned long long acc[8][4];
#pragma unroll
    for (int i = 0; i < 8; ++i)
#pragma unroll
        for (int j = 0; j < 4; ++j)
            acc[i][j] = 0ULL;

    const float* wrow0 = &Wsh[4 * cg];
    const float* wrow1 = &Wsh[4 * cg + 64];

#pragma unroll 4
    for (int k = 0; k < K_IN; ++k) {
        float xs[8];
#pragma unroll
        for (int i = 0; i < 8; ++i)
            xs[i] = Xsh[(rg + 16 * i) * XSTR + k];   // half-warp broadcast, 1 wf

        ulonglong2 wv0 = *(const ulonglong2*)(wrow0 + k * WSTR);
        ulonglong2 wv1 = *(const ulonglong2*)(wrow1 + k * WSTR);
#pragma unroll
        for (int i = 0; i < 8; ++i) {
            unsigned long long xd = dup2(xs[i]);
            ffma2(acc[i][0], xd, wv0.x);
            ffma2(acc[i][1], xd, wv0.y);
            ffma2(acc[i][2], xd, wv1.x);
            ffma2(acc[i][3], xd, wv1.y);
        }
    }

    // epilogue: bias + 2 coalesced STG.128 per row
    float4 b0 = *(const float4*)&bias_sh[4 * cg];
    float4 b1 = *(const float4*)&bias_sh[64 + 4 * cg];

#pragma unroll
    for (int i = 0; i < 8; ++i) {
        int n = n0 + rg + 16 * i;
        float* orow = out + ((size_t)n * C_TOT + c) * O_OUT;
        float2 p0 = unpack2(acc[i][0]);
        float2 p1 = unpack2(acc[i][1]);
        float2 p2 = unpack2(acc[i][2]);
        float2 p3 = unpack2(acc[i][3]);
        float4 v0 = make_float4(p0.x + b0.x, p0.y + b0.y, p1.x + b0.z, p1.y + b0.w);
        float4 v1 = make_float4(p2.x + b1.x, p2.y + b1.y, p3.x + b1.z, p3.y + b1.w);
        *(float4*)&orow[4 * cg]      = v0;
        *(float4*)&orow[64 + 4 * cg] = v1;
    }
}

extern "C" void kernel_launch(void* const* d_in, const int* in_sizes, int n_in,
                              void* d_out, int out_size) {
    const float* x = (const float*)d_in[0];
    const float* W = (const float*)d_in[1];
    const float* b = (const float*)d_in[2];
    float* out = (float*)d_out;

    w_transpose<<<C_TOT, 256>>>(W);

    size_t smem_bytes = (size_t)(128 + TILE_M * XSTR + K_IN * WSTR) * sizeof(float); // 69120
    cudaFuncSetAttribute(dw1d_kernel,
                         cudaFuncAttributeMaxDynamicSharedMemorySize,
                         (int)smem_bytes);
    dim3 grid(N_TOT / TILE_M, C_TOT);
    dw1d_kernel<<<grid, THREADS, smem_bytes>>>(x, b, out);
}